// round 7
// baseline (speedup 1.0000x reference)
#include <cuda_runtime.h>
#include <cuda.h>
#include <cstdint>
#include <dlfcn.h>
#include <math.h>

// ---------------------------------------------------------------------------
// Problem: B=64, H=W=32, CIN=64, HID=128, K=3, L=3, repeats=3.
// Gates=512, M=65536. Out: [h_last | hs_out(3) | cs_out(3)].
// ---------------------------------------------------------------------------
#define BATCH   64
#define HH      32
#define WW      32
#define CIN_X   64
#define HID     128
#define GATES   512
#define MPOS    (BATCH*HH*WW)
#define PLANE   ((size_t)MPOS*HID)
#define KX      (9*CIN_X)              // 576
#define KH      (9*HID)                // 1152

// GEMM tiling: CTA 256(M) x 128(N); 16 warps, warp tile 16 x 128
#define BM          256
#define NTH         512
#define NWARPS      16
#define STAGES      3
#define A_BYTES     32768              // 256 rows x 128B
#define B_BYTES     16384              // 4 boxes x (32 rows x 128B)
#define STAGE_BYTES (A_BYTES + B_BYTES)
#define SM_A(s)     ((s)*STAGE_BYTES)
#define SM_B(s)     (SM_A(s) + A_BYTES)
#define SM_BAR      (STAGES*STAGE_BYTES)           // 147456
#define SMEM_TOTAL  (SM_BAR + 128)

// ---------------------------------------------------------------------------
// Device scratch (tf32-rounded, K-permuted operand copies + state buffers)
// ---------------------------------------------------------------------------
__device__ __align__(1024) float g_WxT[3 * GATES * KX];      // [l][n][k_perm], tf32
__device__ __align__(1024) float g_WhT[3 * GATES * KH];      // [l][n][k_perm], tf32
__device__ __align__(1024) float g_xP [(size_t)MPOS * CIN_X]; // x, tf32 + ch-perm
__device__ __align__(1024) float g_hsP[3 * PLANE];            // hs, tf32 + ch-perm
__device__ __align__(1024) float g_Gx [(size_t)MPOS * GATES];
__device__ __align__(1024) float g_hbuf[2 * PLANE];           // tf32 + ch-perm
__device__ __align__(1024) float g_cbuf[2 * PLANE];           // exact fp32

// ---------------------------------------------------------------------------
// PTX helpers (base-arch features only)
// ---------------------------------------------------------------------------
__device__ __forceinline__ uint32_t smem_u32(const void* p) {
    uint32_t a;
    asm("{ .reg .u64 t; cvta.to.shared.u64 t, %1; cvt.u32.u64 %0, t; }"
        : "=r"(a) : "l"(p));
    return a;
}
#define MBAR_INIT(addr, cnt) \
    asm volatile("mbarrier.init.shared.b64 [%0], %1;" :: "r"(addr), "r"(cnt) : "memory")
#define MBAR_ARRIVE(addr) \
    asm volatile("mbarrier.arrive.shared.b64 _, [%0];" :: "r"(addr) : "memory")
#define MBAR_EXPECT_TX(addr, bytes) \
    asm volatile("mbarrier.arrive.expect_tx.shared.b64 _, [%0], %1;" \
                 :: "r"(addr), "r"(bytes) : "memory")
#define MBAR_WAIT(addr, ph) do {                                              \
    uint32_t _m = (addr), _p = (ph), _d;                                      \
    asm volatile("{\n\t.reg .pred p;\n\t"                                     \
        "mbarrier.try_wait.parity.acquire.cta.shared::cta.b64 p, [%1], %2;\n\t" \
        "selp.b32 %0, 1, 0, p;\n\t}" : "=r"(_d) : "r"(_m), "r"(_p) : "memory");\
    if (!_d) {                                                                \
        asm volatile("{\n\t.reg .pred P1;\n\tWL_%=:\n\t"                      \
            "mbarrier.try_wait.parity.acquire.cta.shared::cta.b64 P1, [%0], %1, 0x989680;\n\t" \
            "@P1 bra.uni WD_%=;\n\tbra.uni WL_%=;\n\tWD_%=:\n\t}"             \
            :: "r"(_m), "r"(_p) : "memory");                                  \
    } } while (0)

#define TMA_LD_5D(dst, map, c0_, c1_, c2_, c3_, c4_, mbar) \
    asm volatile("cp.async.bulk.tensor.5d.shared::cta.global.tile.mbarrier::complete_tx::bytes " \
        "[%0], [%1, {%2, %3, %4, %5, %6}], [%7];" \
        :: "r"(dst), "l"(map), "r"(c0_), "r"(c1_), "r"(c2_), "r"(c3_), "r"(c4_), "r"(mbar) : "memory")
#define TMA_LD_3D(dst, map, c0_, c1_, c2_, mbar) \
    asm volatile("cp.async.bulk.tensor.3d.shared::cta.global.tile.mbarrier::complete_tx::bytes " \
        "[%0], [%1, {%2, %3, %4}], [%5];" \
        :: "r"(dst), "l"(map), "r"(c0_), "r"(c1_), "r"(c2_), "r"(mbar) : "memory")

__device__ __forceinline__ uint2 lds64(uint32_t addr) {
    uint2 r;
    asm("ld.shared.v2.b32 {%0,%1}, [%2];" : "=r"(r.x), "=r"(r.y) : "r"(addr));
    return r;
}

// m16n8k8 tf32 mma (sm_80 base)
__device__ __forceinline__ void mma8(float* d, const uint32_t* a, const uint32_t* b) {
    asm volatile("mma.sync.aligned.m16n8k8.row.col.f32.tf32.tf32.f32 "
        "{%0,%1,%2,%3}, {%4,%5,%6,%7}, {%8,%9}, {%0,%1,%2,%3};"
        : "+f"(d[0]), "+f"(d[1]), "+f"(d[2]), "+f"(d[3])
        : "r"(a[0]), "r"(a[1]), "r"(a[2]), "r"(a[3]), "r"(b[0]), "r"(b[1]));
}

__device__ __forceinline__ float rtf32(float v) {
    uint32_t r; asm("cvt.rna.tf32.f32 %0, %1;" : "=r"(r) : "f"(v));
    return __uint_as_float(r);
}
__device__ __forceinline__ int permpos(int r) { return (r < 4) ? 2*r : 2*(r-4)+1; }
__device__ __forceinline__ float sigm(float v) { return 1.f / (1.f + __expf(-v)); }

// ---------------------------------------------------------------------------
// Fused implicit-GEMM conv via tf32 mma.sync. 16 warps, warp tile 16x128.
// Operands pre-rounded tf32 with K-permuted layout (fragment pair = LDS.64).
// PERM: h output written tf32-rounded + channel-permuted (feeds next conv).
// ---------------------------------------------------------------------------
template<int CPT, int NCHUNK, bool FUSED, bool PERM>
__global__ __launch_bounds__(NTH, 1)
void conv_tc(const __grid_constant__ CUtensorMap a_map,
             const __grid_constant__ CUtensorMap b_map,
             int a_z, int b_z,
             const float* __restrict__ add_src,   // FUSED: Gx[M,512] ; else bias[512]
             const float* __restrict__ c_in,
             float* __restrict__ out0,            // FUSED: h_out ; else Gx
             float* __restrict__ c_out,
             float* __restrict__ h_dup)
{
    extern __shared__ __align__(1024) char smem[];
    const uint32_t sb = smem_u32(smem);
    const int tid  = threadIdx.x;
    const int lane = tid & 31;
    const int wm   = tid >> 5;            // warp -> 16-row M slice

    const uint32_t FULL  = sb + SM_BAR;
    const uint32_t EMPTY = sb + SM_BAR + 32;

    if (tid == 0) {
#pragma unroll
        for (int s = 0; s < STAGES; s++) {
            MBAR_INIT(FULL + 8*s, 1);
            MBAR_INIT(EMPTY + 8*s, NWARPS);
        }
    }
    __syncthreads();

    const int c0   = blockIdx.y * 32;
    const int m0   = blockIdx.x * BM;
    const int bimg = m0 >> 10;
    const int y0   = (m0 >> 5) & 31;

    if (tid == 0) {
#pragma unroll
        for (int kc = 0; kc < STAGES; kc++) {
            const int s = kc;
            MBAR_EXPECT_TX(FULL + 8*s, (uint32_t)STAGE_BYTES);
            const int tap = kc / CPT, cc = (kc % CPT) * 32;
            const int dy = tap / 3 - 1, dx = tap % 3 - 1;
            TMA_LD_5D(sb + SM_A(s), &a_map, cc, dx, y0 + dy, bimg, a_z, FULL + 8*s);
            const int k0 = kc * 32;
#pragma unroll
            for (int g = 0; g < 4; g++)
                TMA_LD_3D(sb + SM_B(s) + g * 4096, &b_map, k0, g * 128 + c0, b_z,
                          FULL + 8*s);
        }
    }

    float acc[16][4];
#pragma unroll
    for (int ni = 0; ni < 16; ni++)
#pragma unroll
        for (int j = 0; j < 4; j++) acc[ni][j] = 0.f;

    const int q4 = lane >> 2;
    const int t4 = lane & 3;
    const uint32_t xorv = (uint32_t)q4 << 4;

    int s = 0, u = 0;
    for (int kc = 0; kc < NCHUNK; kc++) {
        MBAR_WAIT(FULL + 8*s, u);

        const uint32_t aW = sb + SM_A(s) + (uint32_t)wm * 2048 + ((uint32_t)q4 << 7);
        const uint32_t bW = sb + SM_B(s) + ((uint32_t)q4 << 7);

#pragma unroll
        for (int ks = 0; ks < 4; ks++) {
            const uint32_t koff = ((uint32_t)(ks * 32 + t4 * 8)) ^ xorv;

            const uint2 aLo = lds64(aW + koff);          // row q4
            const uint2 aHi = lds64(aW + 1024 + koff);   // row q4+8
            uint2 bfr[16];
#pragma unroll
            for (int ni = 0; ni < 16; ni++)
                bfr[ni] = lds64(bW + (uint32_t)(ni >> 2) * 4096
                                   + (uint32_t)(ni & 3) * 1024 + koff);
            const uint32_t af[4] = {aLo.x, aHi.x, aLo.y, aHi.y};
#pragma unroll
            for (int ni = 0; ni < 16; ni++)
                mma8(acc[ni], af, &bfr[ni].x);
        }

        if (lane == 0) MBAR_ARRIVE(EMPTY + 8*s);

        if (tid == 0 && kc + STAGES < NCHUNK) {
            MBAR_WAIT(EMPTY + 8*s, u);
            MBAR_EXPECT_TX(FULL + 8*s, (uint32_t)STAGE_BYTES);
            const int kn = kc + STAGES;
            const int tap = kn / CPT, cc = (kn % CPT) * 32;
            const int dy = tap / 3 - 1, dx = tap % 3 - 1;
            TMA_LD_5D(sb + SM_A(s), &a_map, cc, dx, y0 + dy, bimg, a_z, FULL + 8*s);
            const int k0 = kn * 32;
#pragma unroll
            for (int g = 0; g < 4; g++)
                TMA_LD_3D(sb + SM_B(s) + g * 4096, &b_map, k0, g * 128 + c0, b_z,
                          FULL + 8*s);
        }

        if (++s == STAGES) { s = 0; u ^= 1; }
    }

    // ------------------------- epilogue -------------------------
    if (FUSED) {
#pragma unroll
        for (int h = 0; h < 2; h++) {
            const int m = m0 + wm * 16 + q4 + 8 * h;
            const int j = 2 * h;
#pragma unroll
            for (int nq = 0; nq < 4; nq++) {
                const int ch = c0 + nq * 8 + t4 * 2;
                const float* gxp = add_src + (size_t)m * GATES + ch;
                const float2 gi = *(const float2*)(gxp);
                const float2 gf = *(const float2*)(gxp + 128);
                const float2 gg = *(const float2*)(gxp + 256);
                const float2 go = *(const float2*)(gxp + 384);
                const float2 cv = *(const float2*)(c_in + (size_t)m * HID + ch);

                const float i0 = acc[nq][j]      + gi.x;
                const float i1 = acc[nq][j+1]    + gi.y;
                const float f0 = acc[4+nq][j]    + gf.x;
                const float f1 = acc[4+nq][j+1]  + gf.y;
                const float g0 = acc[8+nq][j]    + gg.x;
                const float g1 = acc[8+nq][j+1]  + gg.y;
                const float o0 = acc[12+nq][j]   + go.x;
                const float o1 = acc[12+nq][j+1] + go.y;

                float2 cn, hn;
                cn.x = sigm(f0) * cv.x + sigm(i0) * tanhf(g0);
                cn.y = sigm(f1) * cv.y + sigm(i1) * tanhf(g1);
                hn.x = sigm(o0) * tanhf(cn.x);
                hn.y = sigm(o1) * tanhf(cn.y);

                const size_t ob = (size_t)m * HID + ch;
                *(float2*)(c_out + ob) = cn;
                if (PERM) {
                    // tf32-round + channel-permute for next conv's A operand
                    const int base = c0 + nq * 8;
                    const int p0 = (t4 < 2) ? 4 * t4 : 4 * t4 - 7;
                    out0[(size_t)m * HID + base + p0]     = rtf32(hn.x);
                    out0[(size_t)m * HID + base + p0 + 2] = rtf32(hn.y);
                } else {
                    *(float2*)(out0 + ob) = hn;
                    if (h_dup) *(float2*)(h_dup + ob) = hn;
                }
            }
        }
    } else {
#pragma unroll
        for (int h = 0; h < 2; h++) {
            const int m = m0 + wm * 16 + q4 + 8 * h;
            const int j = 2 * h;
#pragma unroll
            for (int ni = 0; ni < 16; ni++) {
                const int gcol = (ni >> 2) * 128 + c0 + (ni & 3) * 8 + t4 * 2;
                const float2 bv = *(const float2*)(add_src + gcol);
                float2 v;
                v.x = acc[ni][j]   + bv.x;
                v.y = acc[ni][j+1] + bv.y;
                *(float2*)(out0 + (size_t)m * GATES + gcol) = v;
            }
        }
    }
}

// ---------------------------------------------------------------------------
// Pre-passes: weight transpose + tf32 round + K-permute; activation copy +
// tf32 round + channel-permute.
// ---------------------------------------------------------------------------
__global__ void prep_w(const float* __restrict__ src, float* __restrict__ dst,
                       int K, int total)
{
    int i = blockIdx.x * blockDim.x + threadIdx.x;
    if (i >= total) return;
    int n = i % GATES;
    int k = (i / GATES) % K;
    int l = i / (GATES * K);
    int kp = (k & ~7) | permpos(k & 7);
    dst[((size_t)l * GATES + n) * K + kp] = rtf32(src[i]);
}

__global__ void prep_a(const float* __restrict__ src, float* __restrict__ dst,
                       int C, size_t total)
{
    size_t i = (size_t)blockIdx.x * blockDim.x + threadIdx.x;
    if (i >= total) return;
    int c = (int)(i % (size_t)C);
    int cp = (c & ~7) | permpos(c & 7);
    dst[i - c + cp] = rtf32(src[i]);
}

// ---------------------------------------------------------------------------
// Host: tensormap encoding via dlopen
// ---------------------------------------------------------------------------
typedef CUresult (*EncFn)(CUtensorMap*, CUtensorMapDataType, cuuint32_t, void*,
                          const cuuint64_t*, const cuuint64_t*, const cuuint32_t*,
                          const cuuint32_t*, CUtensorMapInterleave, CUtensorMapSwizzle,
                          CUtensorMapL2promotion, CUtensorMapFloatOOBfill);
static EncFn get_enc() {
    static EncFn f = nullptr;
    if (!f) {
        void* h = dlopen("libcuda.so.1", RTLD_NOW | RTLD_GLOBAL);
        if (!h) h = dlopen("libcuda.so", RTLD_NOW | RTLD_GLOBAL);
        if (h) f = (EncFn)dlsym(h, "cuTensorMapEncodeTiled");
    }
    return f;
}

static void enc_act5(CUtensorMap* tm, void* base, int C, int Z) {
    cuuint64_t dims[5]    = {(cuuint64_t)C, WW, HH, BATCH, (cuuint64_t)Z};
    cuuint64_t strides[4] = {(cuuint64_t)C * 4, (cuuint64_t)WW * C * 4,
                             (cuuint64_t)HH * WW * C * 4,
                             (cuuint64_t)BATCH * HH * WW * C * 4};
    cuuint32_t box[5] = {32, WW, 8, 1, 1};
    cuuint32_t es[5]  = {1, 1, 1, 1, 1};
    get_enc()(tm, CU_TENSOR_MAP_DATA_TYPE_FLOAT32, 5, base, dims, strides, box, es,
              CU_TENSOR_MAP_INTERLEAVE_NONE, CU_TENSOR_MAP_SWIZZLE_128B,
              CU_TENSOR_MAP_L2_PROMOTION_L2_128B, CU_TENSOR_MAP_FLOAT_OOB_FILL_NONE);
}
static void enc_w3(CUtensorMap* tm, void* base, int K) {
    cuuint64_t dims[3]    = {(cuuint64_t)K, GATES, 3};
    cuuint64_t strides[2] = {(cuuint64_t)K * 4, (cuuint64_t)GATES * K * 4};
    cuuint32_t box[3] = {32, 32, 1};
    cuuint32_t es[3]  = {1, 1, 1};
    get_enc()(tm, CU_TENSOR_MAP_DATA_TYPE_FLOAT32, 3, base, dims, strides, box, es,
              CU_TENSOR_MAP_INTERLEAVE_NONE, CU_TENSOR_MAP_SWIZZLE_128B,
              CU_TENSOR_MAP_L2_PROMOTION_L2_128B, CU_TENSOR_MAP_FLOAT_OOB_FILL_NONE);
}

extern "C" void kernel_launch(void* const* d_in, const int* in_sizes, int n_in,
                              void* d_out, int out_size)
{
    const float* x  = (const float*)d_in[0];
    const float* hs = (const float*)d_in[1];
    const float* cs = (const float*)d_in[2];
    const float* Wx = (const float*)d_in[3];
    const float* Wh = (const float*)d_in[4];
    const float* bb = (const float*)d_in[5];

    float* out    = (float*)d_out;
    float* h_last = out;
    float* hs_out = out + PLANE;
    float* cs_out = out + 4 * PLANE;

    float *WxT, *WhT, *xP, *hsP, *Gx, *hbuf, *cbuf;
    cudaGetSymbolAddress((void**)&WxT,  g_WxT);
    cudaGetSymbolAddress((void**)&WhT,  g_WhT);
    cudaGetSymbolAddress((void**)&xP,   g_xP);
    cudaGetSymbolAddress((void**)&hsP,  g_hsP);
    cudaGetSymbolAddress((void**)&Gx,   g_Gx);
    cudaGetSymbolAddress((void**)&hbuf, g_hbuf);
    cudaGetSymbolAddress((void**)&cbuf, g_cbuf);

    cudaFuncSetAttribute(conv_tc<2, 18, false, false>,
                         cudaFuncAttributeMaxDynamicSharedMemorySize, SMEM_TOTAL);
    cudaFuncSetAttribute(conv_tc<4, 36, true, true>,
                         cudaFuncAttributeMaxDynamicSharedMemorySize, SMEM_TOTAL);
    cudaFuncSetAttribute(conv_tc<4, 36, true, false>,
                         cudaFuncAttributeMaxDynamicSharedMemorySize, SMEM_TOTAL);

    CUtensorMap tm_x, tm_hs, tm_hb, tm_wx, tm_wh;
    enc_act5(&tm_x,  xP,   CIN_X, 1);
    enc_act5(&tm_hs, hsP,  HID,   3);
    enc_act5(&tm_hb, hbuf, HID,   2);
    enc_w3(&tm_wx, WxT, KX);
    enc_w3(&tm_wh, WhT, KH);

    // pre-passes: round + permute weights and input activations
    {
        int tw = 3 * KX * GATES, th = 3 * KH * GATES;
        prep_w<<<(tw + 255) / 256, 256>>>(Wx, WxT, KX, tw);
        prep_w<<<(th + 255) / 256, 256>>>(Wh, WhT, KH, th);
        size_t tx = (size_t)MPOS * CIN_X, ts = 3 * PLANE;
        prep_a<<<(unsigned)((tx + 255) / 256), 256>>>(x,  xP,  CIN_X, tx);
        prep_a<<<(unsigned)((ts + 255) / 256), 256>>>(hs, hsP, HID,   ts);
    }

    const dim3 grid(MPOS / BM, 4);
    for (int l = 0; l < 3; l++) {
        // Gx = conv(x, Wx[l]) + b[l]  (repeat-invariant)
        conv_tc<2, 18, false, false><<<grid, NTH, SMEM_TOTAL>>>(
            tm_x, tm_wx, 0, l, bb + (size_t)l * GATES,
            nullptr, Gx, nullptr, nullptr);

        // r0: hsP[l]/cs[l] -> hbuf0 (perm) / cbuf0
        conv_tc<4, 36, true, true><<<grid, NTH, SMEM_TOTAL>>>(
            tm_hs, tm_wh, l, l, Gx, cs + (size_t)l * PLANE,
            hbuf, cbuf, nullptr);
        // r1: hbuf0/cbuf0 -> hbuf1 (perm) / cbuf1
        conv_tc<4, 36, true, true><<<grid, NTH, SMEM_TOTAL>>>(
            tm_hb, tm_wh, 0, l, Gx, cbuf,
            hbuf + PLANE, cbuf + PLANE, nullptr);
        // r2: hbuf1/cbuf1 -> output slices (exact, natural order)
        conv_tc<4, 36, true, false><<<grid, NTH, SMEM_TOTAL>>>(
            tm_hb, tm_wh, 1, l, Gx, cbuf + PLANE,
            hs_out + (size_t)l * PLANE, cs_out + (size_t)l * PLANE,
            (l == 2) ? h_last : nullptr);
    }
}

// round 9
// speedup vs baseline: 1.4410x; 1.4410x over previous
#include <cuda_runtime.h>
#include <cuda.h>
#include <cstdint>
#include <dlfcn.h>
#include <math.h>

// ---------------------------------------------------------------------------
// Problem: B=64, H=W=32, CIN=64, HID=128, K=3, L=3, repeats=3.
// Gates=512, M=65536. Out: [h_last | hs_out(3) | cs_out(3)].
// ---------------------------------------------------------------------------
#define BATCH   64
#define HH      32
#define WW      32
#define CIN_X   64
#define HID     128
#define GATES   512
#define MPOS    (BATCH*HH*WW)
#define PLANE   ((size_t)MPOS*HID)
#define KX      (9*CIN_X)              // 576
#define KH      (9*HID)                // 1152

// GEMM tiling: CTA 256(M) x 128(N); 8 warps, warp tile 32 x 128
#define BM          256
#define NTH         256
#define STAGES      4
#define A_BYTES     32768              // 256 rows x 128B
#define B_BYTES     16384              // 4 boxes x (32 rows x 128B)
#define STAGE_BYTES (A_BYTES + B_BYTES)
#define SM_A(s)     ((s)*STAGE_BYTES)
#define SM_B(s)     (SM_A(s) + A_BYTES)
#define SM_BAR      (STAGES*STAGE_BYTES)           // 196608
#define SMEM_TOTAL  (SM_BAR + 128)

// ---------------------------------------------------------------------------
// Device scratch. Operands stored tf32-rounded with a custom bank-swizzled
// K layout (see bankperm below); smem image == gmem image (TMA SWIZZLE_NONE).
// ---------------------------------------------------------------------------
__device__ __align__(1024) float g_WxT[3 * GATES * KX];
__device__ __align__(1024) float g_WhT[3 * GATES * KH];
__device__ __align__(1024) float g_xP [(size_t)MPOS * CIN_X];
__device__ __align__(1024) float g_hsP[3 * PLANE];
__device__ __align__(1024) float g_Gx [(size_t)MPOS * GATES];
__device__ __align__(1024) float g_hbuf[2 * PLANE];
__device__ __align__(1024) float g_cbuf[2 * PLANE];

// ---------------------------------------------------------------------------
// PTX helpers
// ---------------------------------------------------------------------------
__device__ __forceinline__ uint32_t smem_u32(const void* p) {
    uint32_t a;
    asm("{ .reg .u64 t; cvta.to.shared.u64 t, %1; cvt.u32.u64 %0, t; }"
        : "=r"(a) : "l"(p));
    return a;
}
#define MBAR_INIT(addr, cnt) \
    asm volatile("mbarrier.init.shared.b64 [%0], %1;" :: "r"(addr), "r"(cnt) : "memory")
#define MBAR_ARRIVE(addr) \
    asm volatile("mbarrier.arrive.shared.b64 _, [%0];" :: "r"(addr) : "memory")
#define MBAR_EXPECT_TX(addr, bytes) \
    asm volatile("mbarrier.arrive.expect_tx.shared.b64 _, [%0], %1;" \
                 :: "r"(addr), "r"(bytes) : "memory")
#define MBAR_WAIT(addr, ph) do {                                              \
    uint32_t _m = (addr), _p = (ph), _d;                                      \
    asm volatile("{\n\t.reg .pred p;\n\t"                                     \
        "mbarrier.try_wait.parity.acquire.cta.shared::cta.b64 p, [%1], %2;\n\t" \
        "selp.b32 %0, 1, 0, p;\n\t}" : "=r"(_d) : "r"(_m), "r"(_p) : "memory");\
    if (!_d) {                                                                \
        asm volatile("{\n\t.reg .pred P1;\n\tWL_%=:\n\t"                      \
            "mbarrier.try_wait.parity.acquire.cta.shared::cta.b64 P1, [%0], %1, 0x989680;\n\t" \
            "@P1 bra.uni WD_%=;\n\tbra.uni WL_%=;\n\tWD_%=:\n\t}"             \
            :: "r"(_m), "r"(_p) : "memory");                                  \
    } } while (0)

#define TMA_LD_5D(dst, map, c0_, c1_, c2_, c3_, c4_, mbar) \
    asm volatile("cp.async.bulk.tensor.5d.shared::cta.global.tile.mbarrier::complete_tx::bytes " \
        "[%0], [%1, {%2, %3, %4, %5, %6}], [%7];" \
        :: "r"(dst), "l"(map), "r"(c0_), "r"(c1_), "r"(c2_), "r"(c3_), "r"(c4_), "r"(mbar) : "memory")
#define TMA_LD_3D(dst, map, c0_, c1_, c2_, mbar) \
    asm volatile("cp.async.bulk.tensor.3d.shared::cta.global.tile.mbarrier::complete_tx::bytes " \
        "[%0], [%1, {%2, %3, %4}], [%5];" \
        :: "r"(dst), "l"(map), "r"(c0_), "r"(c1_), "r"(c2_), "r"(mbar) : "memory")

__device__ __forceinline__ uint2 lds64(uint32_t addr) {
    uint2 r;
    asm("ld.shared.v2.b32 {%0,%1}, [%2];" : "=r"(r.x), "=r"(r.y) : "r"(addr));
    return r;
}

// m16n8k8 tf32 mma (sm_80 base)
__device__ __forceinline__ void mma8(float* d, const uint32_t* a, const uint32_t* b) {
    asm volatile("mma.sync.aligned.m16n8k8.row.col.f32.tf32.tf32.f32 "
        "{%0,%1,%2,%3}, {%4,%5,%6,%7}, {%8,%9}, {%0,%1,%2,%3};"
        : "+f"(d[0]), "+f"(d[1]), "+f"(d[2]), "+f"(d[3])
        : "r"(a[0]), "r"(a[1]), "r"(a[2]), "r"(a[3]), "r"(b[0]), "r"(b[1]));
}

__device__ __forceinline__ float rtf32(float v) {
    uint32_t r; asm("cvt.rna.tf32.f32 %0, %1;" : "=r"(r) : "f"(v));
    return __uint_as_float(r);
}
// within an 8-group: channels (j, j+4) -> positions (2j, 2j+1)  [LDS.64 pairs]
__device__ __forceinline__ int permpos(int r) { return (r < 4) ? 2*r : 2*(r-4)+1; }
// full bank-swizzled position of channel c (0..31 within chunk) for row 'row':
// k-group placed at (c>>3) ^ (row&3); pair-permuted within the group.
__device__ __forceinline__ int bankperm(int c, int row) {
    return ((((c >> 3) & 3) ^ (row & 3)) << 3) | permpos(c & 7);
}
__device__ __forceinline__ float sigm(float v) { return 1.f / (1.f + __expf(-v)); }

// ---------------------------------------------------------------------------
// Fused implicit-GEMM conv via tf32 mma.sync. 8 warps, warp tile 32x128.
// Operand rows (128B) hold a bank-swizzled K layout: fragment loads are
// conflict-free LDS.64 (XOR granule bits 5-6, disjoint from t4*8 bits 3-4).
// Activation swizzle key is GLOBAL x&3; TMA boxes for dx!=0 taps are shifted
// in x, so the A reader compensates with ((q4+dx)&3) per chunk.
// PERM: h output written tf32-rounded + bank-swizzled (feeds next conv).
// ---------------------------------------------------------------------------
template<int CPT, int NCHUNK, bool FUSED, bool PERM>
__global__ __launch_bounds__(NTH, 1)
void conv_tc(const __grid_constant__ CUtensorMap a_map,
             const __grid_constant__ CUtensorMap b_map,
             int a_z, int b_z,
             const float* __restrict__ add_src,   // FUSED: Gx[M,512] ; else bias[512]
             const float* __restrict__ c_in,
             float* __restrict__ out0,            // FUSED: h_out ; else Gx
             float* __restrict__ c_out,
             float* __restrict__ h_dup)
{
    extern __shared__ __align__(1024) char smem[];
    const uint32_t sb = smem_u32(smem);
    const int tid  = threadIdx.x;
    const int lane = tid & 31;
    const int wm   = tid >> 5;

    const uint32_t FULL  = sb + SM_BAR;
    const uint32_t EMPTY = sb + SM_BAR + 32;

    if (tid == 0) {
#pragma unroll
        for (int s = 0; s < STAGES; s++) {
            MBAR_INIT(FULL + 8*s, 1);
            MBAR_INIT(EMPTY + 8*s, 8);
        }
    }
    __syncthreads();

    const int c0   = blockIdx.y * 32;
    const int m0   = blockIdx.x * BM;
    const int bimg = m0 >> 10;
    const int y0   = (m0 >> 5) & 31;

    if (tid == 0) {
#pragma unroll
        for (int kc = 0; kc < STAGES; kc++) {
            const int s = kc;
            MBAR_EXPECT_TX(FULL + 8*s, (uint32_t)STAGE_BYTES);
            const int tap = kc / CPT, cc = (kc % CPT) * 32;
            const int dy = tap / 3 - 1, dx = tap % 3 - 1;
            TMA_LD_5D(sb + SM_A(s), &a_map, cc, dx, y0 + dy, bimg, a_z, FULL + 8*s);
            const int k0 = kc * 32;
#pragma unroll
            for (int g = 0; g < 4; g++)
                TMA_LD_3D(sb + SM_B(s) + g * 4096, &b_map, k0, g * 128 + c0, b_z,
                          FULL + 8*s);
        }
    }

    float acc[2][16][4];
#pragma unroll
    for (int mi = 0; mi < 2; mi++)
#pragma unroll
        for (int ni = 0; ni < 16; ni++)
#pragma unroll
            for (int j = 0; j < 4; j++) acc[mi][ni][j] = 0.f;

    const int q4 = lane >> 2;
    const int t4 = lane & 3;
    const uint32_t xorB = (uint32_t)(q4 & 3) << 5;   // B key: row parity = q4&3

    for (int kc = 0; kc < NCHUNK; kc++) {
        const int s = kc & 3;
        const uint32_t u = (kc >> 2) & 1;
        MBAR_WAIT(FULL + 8*s, u);

        // A key compensation: stored key = global x&3 = (tile row + dx)&3
        const int tap = kc / CPT;
        const int dxA = tap % 3 - 1;
        const uint32_t xorA = (uint32_t)((q4 + dxA) & 3) << 5;

        const uint32_t aW = sb + SM_A(s) + (uint32_t)wm * 4096 + ((uint32_t)q4 << 7);
        const uint32_t bW = sb + SM_B(s) + ((uint32_t)q4 << 7);

#pragma unroll
        for (int ks = 0; ks < 4; ks++) {
            // conflict-free: (t4*8) bits 3-4 disjoint from xor bits 5-6
            const uint32_t koffA = (((uint32_t)(ks * 32)) ^ xorA) + (uint32_t)(t4 * 8);
            const uint32_t koffB = (((uint32_t)(ks * 32)) ^ xorB) + (uint32_t)(t4 * 8);

            uint2 aLo[2], aHi[2];
#pragma unroll
            for (int mi = 0; mi < 2; mi++) {
                aLo[mi] = lds64(aW + (uint32_t)mi * 2048 + koffA);          // row q4
                aHi[mi] = lds64(aW + (uint32_t)mi * 2048 + 1024 + koffA);   // row q4+8
            }
            uint2 bfr[16];
#pragma unroll
            for (int ni = 0; ni < 16; ni++)
                bfr[ni] = lds64(bW + (uint32_t)(ni >> 2) * 4096
                                   + (uint32_t)(ni & 3) * 1024 + koffB);
#pragma unroll
            for (int mi = 0; mi < 2; mi++) {
                const uint32_t af[4] = {aLo[mi].x, aHi[mi].x, aLo[mi].y, aHi[mi].y};
#pragma unroll
                for (int ni = 0; ni < 16; ni++)
                    mma8(acc[mi][ni], af, &bfr[ni].x);
            }
        }

        if (lane == 0) MBAR_ARRIVE(EMPTY + 8*s);

        if (tid == 0 && kc + STAGES < NCHUNK) {
            MBAR_WAIT(EMPTY + 8*s, u);
            MBAR_EXPECT_TX(FULL + 8*s, (uint32_t)STAGE_BYTES);
            const int kn = kc + STAGES;
            const int tapn = kn / CPT, cc = (kn % CPT) * 32;
            const int dy = tapn / 3 - 1, dx = tapn % 3 - 1;
            TMA_LD_5D(sb + SM_A(s), &a_map, cc, dx, y0 + dy, bimg, a_z, FULL + 8*s);
            const int k0 = kn * 32;
#pragma unroll
            for (int g = 0; g < 4; g++)
                TMA_LD_3D(sb + SM_B(s) + g * 4096, &b_map, k0, g * 128 + c0, b_z,
                          FULL + 8*s);
        }
    }

    // ------------------------- epilogue -------------------------
    if (FUSED) {
#pragma unroll
        for (int mi = 0; mi < 2; mi++)
#pragma unroll
            for (int h = 0; h < 2; h++) {
                const int m = m0 + wm * 32 + mi * 16 + q4 + 8 * h;
                const int j = 2 * h;
#pragma unroll
                for (int nq = 0; nq < 4; nq++) {
                    const int ch = c0 + nq * 8 + t4 * 2;
                    const float* gxp = add_src + (size_t)m * GATES + ch;
                    const float2 gi = *(const float2*)(gxp);
                    const float2 gf = *(const float2*)(gxp + 128);
                    const float2 gg = *(const float2*)(gxp + 256);
                    const float2 go = *(const float2*)(gxp + 384);
                    const float2 cv = *(const float2*)(c_in + (size_t)m * HID + ch);

                    const float i0 = acc[mi][nq][j]      + gi.x;
                    const float i1 = acc[mi][nq][j+1]    + gi.y;
                    const float f0 = acc[mi][4+nq][j]    + gf.x;
                    const float f1 = acc[mi][4+nq][j+1]  + gf.y;
                    const float g0 = acc[mi][8+nq][j]    + gg.x;
                    const float g1 = acc[mi][8+nq][j+1]  + gg.y;
                    const float o0 = acc[mi][12+nq][j]   + go.x;
                    const float o1 = acc[mi][12+nq][j+1] + go.y;

                    float2 cn, hn;
                    cn.x = sigm(f0) * cv.x + sigm(i0) * tanhf(g0);
                    cn.y = sigm(f1) * cv.y + sigm(i1) * tanhf(g1);
                    hn.x = sigm(o0) * tanhf(cn.x);
                    hn.y = sigm(o1) * tanhf(cn.y);

                    const size_t ob = (size_t)m * HID + ch;
                    *(float2*)(c_out + ob) = cn;
                    if (PERM) {
                        // tf32-round + bank-swizzle (key = m&3 = x&3) for next conv
                        const int base = c0 + ((nq ^ (m & 3)) << 3);
                        const int p0 = (t4 < 2) ? 4 * t4 : 4 * t4 - 7;
                        out0[(size_t)m * HID + base + p0]     = rtf32(hn.x);
                        out0[(size_t)m * HID + base + p0 + 2] = rtf32(hn.y);
                    } else {
                        *(float2*)(out0 + ob) = hn;
                        if (h_dup) *(float2*)(h_dup + ob) = hn;
                    }
                }
            }
    } else {
#pragma unroll
        for (int mi = 0; mi < 2; mi++)
#pragma unroll
            for (int h = 0; h < 2; h++) {
                const int m = m0 + wm * 32 + mi * 16 + q4 + 8 * h;
                const int j = 2 * h;
#pragma unroll
                for (int ni = 0; ni < 16; ni++) {
                    const int gcol = (ni >> 2) * 128 + c0 + (ni & 3) * 8 + t4 * 2;
                    const float2 bv = *(const float2*)(add_src + gcol);
                    float2 v;
                    v.x = acc[mi][ni][j]   + bv.x;
                    v.y = acc[mi][ni][j+1] + bv.y;
                    *(float2*)(out0 + (size_t)m * GATES + gcol) = v;
                }
            }
    }
}

// ---------------------------------------------------------------------------
// Pre-passes: tf32 round + bank-swizzled K layout.
//   weights: row = n (gate column), swizzle key n&3
//   activations: row = spatial m, swizzle key m&3 (= x&3)
// ---------------------------------------------------------------------------
__global__ void prep_w(const float* __restrict__ src, float* __restrict__ dst,
                       int K, int total)
{
    int i = blockIdx.x * blockDim.x + threadIdx.x;
    if (i >= total) return;
    int n = i % GATES;
    int k = (i / GATES) % K;
    int l = i / (GATES * K);
    int kp = (k & ~31) | bankperm(k & 31, n);
    dst[((size_t)l * GATES + n) * K + kp] = rtf32(src[i]);
}

__global__ void prep_a(const float* __restrict__ src, float* __restrict__ dst,
                       int C, size_t total)
{
    size_t i = (size_t)blockIdx.x * blockDim.x + threadIdx.x;
    if (i >= total) return;
    int c = (int)(i % (size_t)C);
    int m = (int)((i / (size_t)C) & 3);       // row parity = x&3
    int cp = (c & ~31) | bankperm(c & 31, m);
    dst[i - c + cp] = rtf32(src[i]);
}

// ---------------------------------------------------------------------------
// Host: tensormap encoding via dlopen
// ---------------------------------------------------------------------------
typedef CUresult (*EncFn)(CUtensorMap*, CUtensorMapDataType, cuuint32_t, void*,
                          const cuuint64_t*, const cuuint64_t*, const cuuint32_t*,
                          const cuuint32_t*, CUtensorMapInterleave, CUtensorMapSwizzle,
                          CUtensorMapL2promotion, CUtensorMapFloatOOBfill);
static EncFn get_enc() {
    static EncFn f = nullptr;
    if (!f) {
        void* h = dlopen("libcuda.so.1", RTLD_NOW | RTLD_GLOBAL);
        if (!h) h = dlopen("libcuda.so", RTLD_NOW | RTLD_GLOBAL);
        if (h) f = (EncFn)dlsym(h, "cuTensorMapEncodeTiled");
    }
    return f;
}

static void enc_act5(CUtensorMap* tm, void* base, int C, int Z) {
    cuuint64_t dims[5]    = {(cuuint64_t)C, WW, HH, BATCH, (cuuint64_t)Z};
    cuuint64_t strides[4] = {(cuuint64_t)C * 4, (cuuint64_t)WW * C * 4,
                             (cuuint64_t)HH * WW * C * 4,
                             (cuuint64_t)BATCH * HH * WW * C * 4};
    cuuint32_t box[5] = {32, WW, 8, 1, 1};
    cuuint32_t es[5]  = {1, 1, 1, 1, 1};
    get_enc()(tm, CU_TENSOR_MAP_DATA_TYPE_FLOAT32, 5, base, dims, strides, box, es,
              CU_TENSOR_MAP_INTERLEAVE_NONE, CU_TENSOR_MAP_SWIZZLE_NONE,
              CU_TENSOR_MAP_L2_PROMOTION_L2_128B, CU_TENSOR_MAP_FLOAT_OOB_FILL_NONE);
}
static void enc_w3(CUtensorMap* tm, void* base, int K) {
    cuuint64_t dims[3]    = {(cuuint64_t)K, GATES, 3};
    cuuint64_t strides[2] = {(cuuint64_t)K * 4, (cuuint64_t)GATES * K * 4};
    cuuint32_t box[3] = {32, 32, 1};
    cuuint32_t es[3]  = {1, 1, 1};
    get_enc()(tm, CU_TENSOR_MAP_DATA_TYPE_FLOAT32, 3, base, dims, strides, box, es,
              CU_TENSOR_MAP_INTERLEAVE_NONE, CU_TENSOR_MAP_SWIZZLE_NONE,
              CU_TENSOR_MAP_L2_PROMOTION_L2_128B, CU_TENSOR_MAP_FLOAT_OOB_FILL_NONE);
}

extern "C" void kernel_launch(void* const* d_in, const int* in_sizes, int n_in,
                              void* d_out, int out_size)
{
    const float* x  = (const float*)d_in[0];
    const float* hs = (const float*)d_in[1];
    const float* cs = (const float*)d_in[2];
    const float* Wx = (const float*)d_in[3];
    const float* Wh = (const float*)d_in[4];
    const float* bb = (const float*)d_in[5];

    float* out    = (float*)d_out;
    float* h_last = out;
    float* hs_out = out + PLANE;
    float* cs_out = out + 4 * PLANE;

    float *WxT, *WhT, *xP, *hsP, *Gx, *hbuf, *cbuf;
    cudaGetSymbolAddress((void**)&WxT,  g_WxT);
    cudaGetSymbolAddress((void**)&WhT,  g_WhT);
    cudaGetSymbolAddress((void**)&xP,   g_xP);
    cudaGetSymbolAddress((void**)&hsP,  g_hsP);
    cudaGetSymbolAddress((void**)&Gx,   g_Gx);
    cudaGetSymbolAddress((void**)&hbuf, g_hbuf);
    cudaGetSymbolAddress((void**)&cbuf, g_cbuf);

    cudaFuncSetAttribute(conv_tc<2, 18, false, false>,
                         cudaFuncAttributeMaxDynamicSharedMemorySize, SMEM_TOTAL);
    cudaFuncSetAttribute(conv_tc<4, 36, true, true>,
                         cudaFuncAttributeMaxDynamicSharedMemorySize, SMEM_TOTAL);
    cudaFuncSetAttribute(conv_tc<4, 36, true, false>,
                         cudaFuncAttributeMaxDynamicSharedMemorySize, SMEM_TOTAL);

    CUtensorMap tm_x, tm_hs, tm_hb, tm_wx, tm_wh;
    enc_act5(&tm_x,  xP,   CIN_X, 1);
    enc_act5(&tm_hs, hsP,  HID,   3);
    enc_act5(&tm_hb, hbuf, HID,   2);
    enc_w3(&tm_wx, WxT, KX);
    enc_w3(&tm_wh, WhT, KH);

    // pre-passes: round + bank-swizzle weights and input activations
    {
        int tw = 3 * KX * GATES, th = 3 * KH * GATES;
        prep_w<<<(tw + 255) / 256, 256>>>(Wx, WxT, KX, tw);
        prep_w<<<(th + 255) / 256, 256>>>(Wh, WhT, KH, th);
        size_t tx = (size_t)MPOS * CIN_X, ts = 3 * PLANE;
        prep_a<<<(unsigned)((tx + 255) / 256), 256>>>(x,  xP,  CIN_X, tx);
        prep_a<<<(unsigned)((ts + 255) / 256), 256>>>(hs, hsP, HID,   ts);
    }

    const dim3 grid(MPOS / BM, 4);
    for (int l = 0; l < 3; l++) {
        // Gx = conv(x, Wx[l]) + b[l]  (repeat-invariant)
        conv_tc<2, 18, false, false><<<grid, NTH, SMEM_TOTAL>>>(
            tm_x, tm_wx, 0, l, bb + (size_t)l * GATES,
            nullptr, Gx, nullptr, nullptr);

        // r0: hsP[l]/cs[l] -> hbuf0 (bank-swizzled) / cbuf0
        conv_tc<4, 36, true, true><<<grid, NTH, SMEM_TOTAL>>>(
            tm_hs, tm_wh, l, l, Gx, cs + (size_t)l * PLANE,
            hbuf, cbuf, nullptr);
        // r1: hbuf0/cbuf0 -> hbuf1 (bank-swizzled) / cbuf1
        conv_tc<4, 36, true, true><<<grid, NTH, SMEM_TOTAL>>>(
            tm_hb, tm_wh, 0, l, Gx, cbuf,
            hbuf + PLANE, cbuf + PLANE, nullptr);
        // r2: hbuf1/cbuf1 -> output slices (exact, natural order)
        conv_tc<4, 36, true, false><<<grid, NTH, SMEM_TOTAL>>>(
            tm_hb, tm_wh, 1, l, Gx, cbuf + PLANE,
            hs_out + (size_t)l * PLANE, cs_out + (size_t)l * PLANE,
            (l == 2) ? h_last : nullptr);
    }
}